// round 5
// baseline (speedup 1.0000x reference)
#include <cuda_runtime.h>
#include <cuda_bf16.h>
#include <math.h>
#include <stdint.h>

// Problem constants
#define NROWS   65536      // 32*2048 flattened z rows
#define EDIM    256
#define NE      1024
#define LOSSPARTS 8192

// Full-concat output layout (tuple order: loss, z_q_st, idx, perplexity, N_t, m_t)
#define OFF_LOSS 0
#define OFF_ZQ   1
#define OFF_IDX  16777217
#define OFF_PERP 16842753
#define OFF_NT   16842754
#define OFF_MT   16843778
#define OUT_TOTAL 17105922

// ---------------- scratch (__device__ globals: no allocations allowed) ----------
__device__ int    g_idx[NROWS];
__device__ float  g_rowa[NROWS];        // fl32(||z_row||^2), correctly rounded
__device__ float  g_enorm[NE];          // fl32(||e_j||^2)
__device__ float  g_counts[NE];
__device__ float  g_sums[NE * EDIM];
__device__ double g_losspart[LOSSPARTS];

// ---------------- kernel: zero the accumulators --------------------------------
__global__ void zero_kernel() {
    int i = blockIdx.x * blockDim.x + threadIdx.x;     // grid covers 262144
    if (i < NE * EDIM) g_sums[i] = 0.0f;
    if (i < NE)        g_counts[i] = 0.0f;
    if (i < LOSSPARTS) g_losspart[i] = 0.0;
}

// ---------------- kernel: code norms ||e_j||^2 ----------------------------------
__global__ void enorm_kernel(const float* __restrict__ emb) {
    int i = blockIdx.x * blockDim.x + threadIdx.x;
    if (i >= NE) return;
    const float4* er = reinterpret_cast<const float4*>(emb + (size_t)i * EDIM);
    double s = 0.0;
    #pragma unroll 8
    for (int q = 0; q < EDIM / 4; ++q) {
        float4 v = er[q];
        s += (double)v.x * v.x; s += (double)v.y * v.y;
        s += (double)v.z * v.z; s += (double)v.w * v.w;
    }
    g_enorm[i] = (float)s;
}

// ---------------- kernel: row norms ||z_i||^2 (warp per row) --------------------
__global__ void rownorm_kernel(const float* __restrict__ z) {
    int tid  = threadIdx.x;
    int lane = tid & 31;
    int row  = blockIdx.x * 8 + (tid >> 5);
    if (row >= NROWS) return;
    const float4* zr = reinterpret_cast<const float4*>(z + (size_t)row * EDIM);
    double s = 0.0;
    #pragma unroll
    for (int j = 0; j < 2; ++j) {
        float4 v = zr[lane + 32 * j];
        s += (double)v.x * v.x; s += (double)v.y * v.y;
        s += (double)v.z * v.z; s += (double)v.w * v.w;
    }
    #pragma unroll
    for (int off = 16; off; off >>= 1)
        s += __shfl_down_sync(0xffffffffu, s, off);
    if (lane == 0) g_rowa[row] = (float)s;
}

// ---------------- kernel: fused distance GEMM + argmin --------------------------
// Block: 256 threads, 32 rows x all 1024 codes.
// Warp w handles rows [4w, 4w+4); lane l handles codes {chunk*128 + 4l .. +3}.
// smem: zs[k][row] 32x32 (4KB), es[k][code] 32x128 (16KB).
__global__ __launch_bounds__(256, 2)
void argmin_kernel(const float* __restrict__ z, const float* __restrict__ emb) {
    __shared__ float zs[32 * 32];
    __shared__ float es[32 * 128];

    const int tid  = threadIdx.x;
    const int lane = tid & 31;
    const int rowq = tid >> 5;                 // 0..7
    const int rowbase = blockIdx.x * 32;

    float afr[4];
    #pragma unroll
    for (int r = 0; r < 4; ++r)
        afr[r] = g_rowa[rowbase + rowq * 4 + r];

    float bestv[4]; int besti[4];
    #pragma unroll
    for (int r = 0; r < 4; ++r) { bestv[r] = __int_as_float(0x7f800000); besti[r] = 0; }

    for (int cc = 0; cc < 8; ++cc) {           // 8 code chunks of 128
        float acc[4][4];
        #pragma unroll
        for (int r = 0; r < 4; ++r)
            #pragma unroll
            for (int c = 0; c < 4; ++c) acc[r][c] = 0.0f;

        for (int kb = 0; kb < EDIM; kb += 32) {
            __syncthreads();
            // load z tile: 32 rows x 32 k (transposed)
            {
                int r  = tid >> 3;             // 0..31
                int k4 = (tid & 7) * 4;        // 0..28
                float4 v = *reinterpret_cast<const float4*>(
                    z + (size_t)(rowbase + r) * EDIM + kb + k4);
                zs[(k4 + 0) * 32 + r] = v.x;
                zs[(k4 + 1) * 32 + r] = v.y;
                zs[(k4 + 2) * 32 + r] = v.z;
                zs[(k4 + 3) * 32 + r] = v.w;
            }
            // load e tile: 128 codes x 32 k (transposed)
            {
                int ct = tid & 127;
                int kh = tid >> 7;             // 0/1
                const float* src = emb + (size_t)(cc * 128 + ct) * EDIM + kb + kh * 16;
                #pragma unroll
                for (int q = 0; q < 4; ++q) {
                    float4 v = *reinterpret_cast<const float4*>(src + q * 4);
                    int k0 = kh * 16 + q * 4;
                    es[(k0 + 0) * 128 + ct] = v.x;
                    es[(k0 + 1) * 128 + ct] = v.y;
                    es[(k0 + 2) * 128 + ct] = v.z;
                    es[(k0 + 3) * 128 + ct] = v.w;
                }
            }
            __syncthreads();

            #pragma unroll
            for (int k = 0; k < 32; k += 2) {
                float4 za = *reinterpret_cast<const float4*>(&zs[k * 32 + rowq * 4]);
                float4 zb = *reinterpret_cast<const float4*>(&zs[(k + 1) * 32 + rowq * 4]);
                float4 e0 = *reinterpret_cast<const float4*>(&es[k * 128 + lane * 4]);
                float4 e1 = *reinterpret_cast<const float4*>(&es[(k + 1) * 128 + lane * 4]);
                float zra[4] = { za.x, za.y, za.z, za.w };
                float zrb[4] = { zb.x, zb.y, zb.z, zb.w };
                float ea[4]  = { e0.x, e0.y, e0.z, e0.w };
                float eb[4]  = { e1.x, e1.y, e1.z, e1.w };
                #pragma unroll
                for (int r = 0; r < 4; ++r)
                    #pragma unroll
                    for (int c = 0; c < 4; ++c) {
                        acc[r][c] = fmaf(zra[r], ea[c], acc[r][c]);
                        acc[r][c] = fmaf(zrb[r], eb[c], acc[r][c]);
                    }
            }
        }

        // finalize this chunk's 4 codes per thread (codes ascending -> first-min tie)
        #pragma unroll
        for (int c = 0; c < 4; ++c) {
            int code = cc * 128 + lane * 4 + c;
            float b  = g_enorm[code];
            #pragma unroll
            for (int r = 0; r < 4; ++r) {
                // exact fp32 emulation of fl(fl(a+b) - 2*m)
                float dd = (afr[r] + b) - 2.0f * acc[r][c];
                if (dd < bestv[r]) { bestv[r] = dd; besti[r] = code; }
            }
        }
    }

    // warp argmin reduce (lowest index on ties)
    #pragma unroll
    for (int r = 0; r < 4; ++r) {
        float v = bestv[r]; int id = besti[r];
        #pragma unroll
        for (int off = 16; off; off >>= 1) {
            float ov = __shfl_down_sync(0xffffffffu, v, off);
            int   oi = __shfl_down_sync(0xffffffffu, id, off);
            if (ov < v || (ov == v && oi < id)) { v = ov; id = oi; }
        }
        if (lane == 0) {
            int row = rowbase + rowq * 4 + r;
            g_idx[row] = id;
            atomicAdd(&g_counts[id], 1.0f);
        }
    }
}

// ---------------- kernel: gather z_q, straight-through, loss, segment sums ------
__global__ void scatter_kernel(const float* __restrict__ z, const float* __restrict__ emb,
                               float* __restrict__ out, int out_size,
                               int zq_off, int idx_off) {
    __shared__ double wsum[8];
    int tid  = threadIdx.x;
    int lane = tid & 31;
    int w    = tid >> 5;
    int row  = blockIdx.x * 8 + w;

    int id = g_idx[row];
    const float4* zr = reinterpret_cast<const float4*>(z + (size_t)row * EDIM);
    const float4* er = reinterpret_cast<const float4*>(emb + (size_t)id * EDIM);

    double ls = 0.0;
    #pragma unroll
    for (int j = 0; j < 2; ++j) {
        int c4 = lane + 32 * j;
        float4 zv = zr[c4];
        float4 ev = er[c4];
        // straight-through: fl(z + fl(z_q - z))
        float dx = ev.x - zv.x, dy = ev.y - zv.y, dz = ev.z - zv.z, dw = ev.w - zv.w;
        if (zq_off >= 0) {
            int base = zq_off + row * EDIM + c4 * 4;
            if (base + 3 < out_size) {
                out[base + 0] = zv.x + dx;
                out[base + 1] = zv.y + dy;
                out[base + 2] = zv.z + dz;
                out[base + 3] = zv.w + dw;
            }
        }
        ls += (double)dx * dx + (double)dy * dy + (double)dz * dz + (double)dw * dw;
        int sb = id * EDIM + c4 * 4;
        atomicAdd(&g_sums[sb + 0], zv.x);
        atomicAdd(&g_sums[sb + 1], zv.y);
        atomicAdd(&g_sums[sb + 2], zv.z);
        atomicAdd(&g_sums[sb + 3], zv.w);
    }
    if (lane == 0 && idx_off >= 0) {
        int p = idx_off + row;
        if (p < out_size) out[p] = (float)id;
    }
    #pragma unroll
    for (int off = 16; off; off >>= 1)
        ls += __shfl_down_sync(0xffffffffu, ls, off);
    if (lane == 0) wsum[w] = ls;
    __syncthreads();
    if (tid == 0) {
        double t = 0.0;
        #pragma unroll
        for (int i = 0; i < 8; ++i) t += wsum[i];
        g_losspart[blockIdx.x] = t;
    }
}

// ---------------- kernel: m_t EMA update ---------------------------------------
__global__ void mt_kernel(const float* __restrict__ m_t, float* __restrict__ out,
                          int out_size, int mt_off) {
    int i = blockIdx.x * blockDim.x + threadIdx.x;
    if (i >= NE * EDIM || mt_off < 0) return;
    int j = i >> 8;
    float m = m_t[i];
    float val = (g_counts[j] > 0.0f) ? (m * 0.99f + g_sums[i] * 0.01f) : m;
    int p = mt_off + i;
    if (p < out_size) out[p] = val;
}

// ---------------- kernel: loss / perplexity / N_t -------------------------------
__global__ void finalize_kernel(const float* __restrict__ N_t, float* __restrict__ out,
                                int out_size, int loss_off, int perp_off, int nt_off) {
    __shared__ double red[1024];
    int tid = threadIdx.x;

    // loss sum
    double s = 0.0;
    for (int i = tid; i < LOSSPARTS; i += 1024) s += g_losspart[i];
    red[tid] = s;
    __syncthreads();
    for (int st = 512; st > 0; st >>= 1) {
        if (tid < st) red[tid] += red[tid + st];
        __syncthreads();
    }
    double loss_sum = red[0];
    __syncthreads();

    // perplexity sum
    float c = g_counts[tid];
    float em = c * (1.0f / 65536.0f);
    red[tid] = (double)(em * logf(em + 1e-10f));
    __syncthreads();
    for (int st = 512; st > 0; st >>= 1) {
        if (tid < st) red[tid] += red[tid + st];
        __syncthreads();
    }
    if (tid == 0) {
        if (loss_off >= 0 && loss_off < out_size)
            out[loss_off] = 0.25f * (float)(loss_sum / 16777216.0);
        if (perp_off >= 0 && perp_off < out_size)
            out[perp_off] = expf(-(float)red[0]);
    }
    if (nt_off >= 0) {
        float nt = N_t[tid];
        float val = (c > 0.0f) ? (nt * 0.99f + c * 0.01f) : nt;
        int p = nt_off + tid;
        if (p < out_size) out[p] = val;
    }
}

// ---------------- launcher -------------------------------------------------------
extern "C" void kernel_launch(void* const* d_in, const int* in_sizes, int n_in,
                              void* d_out, int out_size) {
    const float* z   = (const float*)d_in[0];   // [32,2048,256]
    const float* emb = (const float*)d_in[1];   // [1024,256]
    const float* N_t = (const float*)d_in[2];   // [1024]
    const float* m_t = (const float*)d_in[3];   // [1024,256]
    float* out = (float*)d_out;

    // output layout selection (robust to harness flattening conventions)
    int loss_off, zq_off, idx_off, perp_off, nt_off, mt_off;
    if (out_size == NROWS * EDIM) {             // z_q_st only
        loss_off = -1; zq_off = 0; idx_off = -1; perp_off = -1; nt_off = -1; mt_off = -1;
    } else if (out_size == NROWS) {             // idx only
        loss_off = -1; zq_off = -1; idx_off = 0; perp_off = -1; nt_off = -1; mt_off = -1;
    } else {                                    // full tuple concat (clipped)
        loss_off = OFF_LOSS; zq_off = OFF_ZQ; idx_off = OFF_IDX;
        perp_off = OFF_PERP; nt_off = OFF_NT; mt_off = OFF_MT;
    }

    zero_kernel<<<1024, 256>>>();
    enorm_kernel<<<4, 256>>>(emb);
    rownorm_kernel<<<NROWS / 8, 256>>>(z);
    argmin_kernel<<<NROWS / 32, 256>>>(z, emb);
    scatter_kernel<<<NROWS / 8, 256>>>(z, emb, out, out_size, zq_off, idx_off);
    mt_kernel<<<NE * EDIM / 256, 256>>>(m_t, out, out_size, mt_off);
    finalize_kernel<<<1, 1024>>>(N_t, out, out_size, loss_off, perp_off, nt_off);
}

// round 6
// speedup vs baseline: 1.3297x; 1.3297x over previous
#include <cuda_runtime.h>
#include <cuda_bf16.h>
#include <math.h>
#include <stdint.h>

typedef unsigned long long u64;

// Problem constants
#define NROWS   65536      // 32*2048 flattened z rows
#define EDIM    256
#define NE      1024
#define LOSSPARTS 8192

// Full-concat output layout (tuple order: loss, z_q_st, idx, perplexity, N_t, m_t)
#define OFF_LOSS 0
#define OFF_ZQ   1
#define OFF_IDX  16777217
#define OFF_PERP 16842753
#define OFF_NT   16842754
#define OFF_MT   16843778

// ---------------- scratch (__device__ globals: no allocations allowed) ----------
__device__ int    g_idx[NROWS];
__device__ float  g_rowa[NROWS];        // fl32(||z_row||^2)
__device__ float  g_enorm[NE];          // fl32(||e_j||^2)
__device__ float  g_counts[NE];
__device__ float  g_sums[NE * EDIM];
__device__ double g_losspart[LOSSPARTS];

// ---------------- packed fp32x2 helpers (Blackwell dual-FP32 pipe) --------------
__device__ __forceinline__ u64 ffma2(u64 a, u64 b, u64 c) {
    u64 d;
    asm("fma.rn.f32x2 %0, %1, %2, %3;" : "=l"(d) : "l"(a), "l"(b), "l"(c));
    return d;
}
__device__ __forceinline__ u64 dupf(float x) {
    unsigned xi = __float_as_uint(x);
    u64 d;
    asm("mov.b64 %0, {%1, %1};" : "=l"(d) : "r"(xi));
    return d;
}
__device__ __forceinline__ float2 unpack2(u64 v) {
    unsigned lo, hi;
    asm("mov.b64 {%0, %1}, %2;" : "=r"(lo), "=r"(hi) : "l"(v));
    float2 r; r.x = __uint_as_float(lo); r.y = __uint_as_float(hi);
    return r;
}

// ---------------- kernel: zero the accumulators --------------------------------
__global__ void zero_kernel() {
    int i = blockIdx.x * blockDim.x + threadIdx.x;     // grid covers 262144
    if (i < NE * EDIM) g_sums[i] = 0.0f;
    if (i < NE)        g_counts[i] = 0.0f;
    if (i < LOSSPARTS) g_losspart[i] = 0.0;
}

// ---------------- kernel: code norms ||e_j||^2 ----------------------------------
__global__ void enorm_kernel(const float* __restrict__ emb) {
    int i = blockIdx.x * blockDim.x + threadIdx.x;
    if (i >= NE) return;
    const float4* er = reinterpret_cast<const float4*>(emb + (size_t)i * EDIM);
    double s = 0.0;
    #pragma unroll 8
    for (int q = 0; q < EDIM / 4; ++q) {
        float4 v = er[q];
        s += (double)v.x * v.x; s += (double)v.y * v.y;
        s += (double)v.z * v.z; s += (double)v.w * v.w;
    }
    g_enorm[i] = (float)s;
}

// ---------------- kernel: row norms ||z_i||^2 (warp per row) --------------------
__global__ void rownorm_kernel(const float* __restrict__ z) {
    int tid  = threadIdx.x;
    int lane = tid & 31;
    int row  = blockIdx.x * 8 + (tid >> 5);
    if (row >= NROWS) return;
    const float4* zr = reinterpret_cast<const float4*>(z + (size_t)row * EDIM);
    double s = 0.0;
    #pragma unroll
    for (int j = 0; j < 2; ++j) {
        float4 v = zr[lane + 32 * j];
        s += (double)v.x * v.x; s += (double)v.y * v.y;
        s += (double)v.z * v.z; s += (double)v.w * v.w;
    }
    #pragma unroll
    for (int off = 16; off; off >>= 1)
        s += __shfl_down_sync(0xffffffffu, s, off);
    if (lane == 0) g_rowa[row] = (float)s;
}

// ---------------- kernel: fused distance GEMM + argmin (fp32x2) -----------------
// Block: 256 threads (8 warps), covers 64 rows x 1024 codes (4 chunks of 256).
// Warp w owns rows [8w, 8w+8); lane l owns codes {chunk*256 + 64j + 2l, +1 : j=0..3}.
// smem: zs (duplicated pairs) [32k][64row] u64 = 16KB; es [32k][256code] f32 = 32KB.
// Accumulators: 8 rows x 4 code-pairs of f32x2 = 32 u64 regs.
__global__ __launch_bounds__(256, 2)
void argmin_kernel(const float* __restrict__ z, const float* __restrict__ emb) {
    __shared__ u64   zs[32 * 64];     // [k][row] as (v,v) pairs
    __shared__ float es[32 * 256];    // [k][code]

    const int tid  = threadIdx.x;
    const int lane = tid & 31;
    const int warp = tid >> 5;                  // 0..7: row group
    const int rowbase = blockIdx.x * 64;
    const int myrow0  = rowbase + warp * 8;

    float bestv[8]; int besti[8];
    #pragma unroll
    for (int r = 0; r < 8; ++r) { bestv[r] = __int_as_float(0x7f800000); besti[r] = 0; }

    // z tile loader mapping: 256 threads cover 64 rows x 32 k (8 floats each)
    const int zl_row = tid >> 2;                // 0..63
    const int zl_k   = (tid & 3) * 8;           // 0,8,16,24

    const u64* es64 = reinterpret_cast<const u64*>(es);

    for (int cc = 0; cc < 4; ++cc) {
        u64 acc[8][4];
        #pragma unroll
        for (int r = 0; r < 8; ++r)
            #pragma unroll
            for (int j = 0; j < 4; ++j) acc[r][j] = 0ull;

        for (int kb = 0; kb < EDIM; kb += 32) {
            __syncthreads();
            // load z tile, pre-duplicated (v,v)
            {
                const float4* src = reinterpret_cast<const float4*>(
                    z + (size_t)(rowbase + zl_row) * EDIM + kb + zl_k);
                float4 a = src[0], b = src[1];
                zs[(zl_k + 0) * 64 + zl_row] = dupf(a.x);
                zs[(zl_k + 1) * 64 + zl_row] = dupf(a.y);
                zs[(zl_k + 2) * 64 + zl_row] = dupf(a.z);
                zs[(zl_k + 3) * 64 + zl_row] = dupf(a.w);
                zs[(zl_k + 4) * 64 + zl_row] = dupf(b.x);
                zs[(zl_k + 5) * 64 + zl_row] = dupf(b.y);
                zs[(zl_k + 6) * 64 + zl_row] = dupf(b.z);
                zs[(zl_k + 7) * 64 + zl_row] = dupf(b.w);
            }
            // load e tile transposed: code = cc*256 + tid, 32 k's
            {
                const float4* src = reinterpret_cast<const float4*>(
                    emb + (size_t)(cc * 256 + tid) * EDIM + kb);
                #pragma unroll
                for (int q = 0; q < 8; ++q) {
                    float4 v = src[q];
                    es[(q * 4 + 0) * 256 + tid] = v.x;
                    es[(q * 4 + 1) * 256 + tid] = v.y;
                    es[(q * 4 + 2) * 256 + tid] = v.z;
                    es[(q * 4 + 3) * 256 + tid] = v.w;
                }
            }
            __syncthreads();

            #pragma unroll 8
            for (int k = 0; k < 32; ++k) {
                // z: 4 broadcast LDS.128 -> 8 duplicated row values
                const ulonglong2* zp = reinterpret_cast<const ulonglong2*>(
                    &zs[k * 64 + warp * 8]);
                ulonglong2 z01 = zp[0], z23 = zp[1], z45 = zp[2], z67 = zp[3];
                // e: 4 conflict-free LDS.64 -> 4 consecutive-code pairs
                u64 e0 = es64[k * 128 + lane];
                u64 e1 = es64[k * 128 + lane + 32];
                u64 e2 = es64[k * 128 + lane + 64];
                u64 e3 = es64[k * 128 + lane + 96];
                u64 zr[8] = { z01.x, z01.y, z23.x, z23.y, z45.x, z45.y, z67.x, z67.y };
                #pragma unroll
                for (int r = 0; r < 8; ++r) {
                    acc[r][0] = ffma2(zr[r], e0, acc[r][0]);
                    acc[r][1] = ffma2(zr[r], e1, acc[r][1]);
                    acc[r][2] = ffma2(zr[r], e2, acc[r][2]);
                    acc[r][3] = ffma2(zr[r], e3, acc[r][3]);
                }
            }
        }

        // epilogue for this 256-code chunk (codes ascending -> first-min tie kept)
        #pragma unroll
        for (int j = 0; j < 4; ++j) {
            int c0 = cc * 256 + j * 64 + lane * 2;
            float2 bb = *reinterpret_cast<const float2*>(&g_enorm[c0]);
            #pragma unroll
            for (int r = 0; r < 8; ++r) {
                float a  = g_rowa[myrow0 + r];
                float2 m = unpack2(acc[r][j]);
                float d0 = (a + bb.x) - 2.0f * m.x;
                float d1 = (a + bb.y) - 2.0f * m.y;
                if (d0 < bestv[r]) { bestv[r] = d0; besti[r] = c0; }
                if (d1 < bestv[r]) { bestv[r] = d1; besti[r] = c0 + 1; }
            }
        }
    }

    // warp argmin reduce (lowest index on ties)
    #pragma unroll
    for (int r = 0; r < 8; ++r) {
        float v = bestv[r]; int id = besti[r];
        #pragma unroll
        for (int off = 16; off; off >>= 1) {
            float ov = __shfl_down_sync(0xffffffffu, v, off);
            int   oi = __shfl_down_sync(0xffffffffu, id, off);
            if (ov < v || (ov == v && oi < id)) { v = ov; id = oi; }
        }
        if (lane == 0) {
            g_idx[myrow0 + r] = id;
            atomicAdd(&g_counts[id], 1.0f);
        }
    }
}

// ---------------- kernel: gather z_q, straight-through, loss, segment sums ------
__global__ void scatter_kernel(const float* __restrict__ z, const float* __restrict__ emb,
                               float* __restrict__ out, int out_size,
                               int zq_off, int idx_off) {
    __shared__ double wsum[8];
    int tid  = threadIdx.x;
    int lane = tid & 31;
    int w    = tid >> 5;
    int row  = blockIdx.x * 8 + w;

    int id = g_idx[row];
    const float4* zr = reinterpret_cast<const float4*>(z + (size_t)row * EDIM);
    const float4* er = reinterpret_cast<const float4*>(emb + (size_t)id * EDIM);

    double ls = 0.0;
    #pragma unroll
    for (int j = 0; j < 2; ++j) {
        int c4 = lane + 32 * j;
        float4 zv = zr[c4];
        float4 ev = er[c4];
        float dx = ev.x - zv.x, dy = ev.y - zv.y, dz = ev.z - zv.z, dw = ev.w - zv.w;
        if (zq_off >= 0) {
            int base = zq_off + row * EDIM + c4 * 4;
            if (base + 3 < out_size) {
                out[base + 0] = zv.x + dx;
                out[base + 1] = zv.y + dy;
                out[base + 2] = zv.z + dz;
                out[base + 3] = zv.w + dw;
            }
        }
        ls += (double)dx * dx + (double)dy * dy + (double)dz * dz + (double)dw * dw;
        int sb = id * EDIM + c4 * 4;
        atomicAdd(&g_sums[sb + 0], zv.x);
        atomicAdd(&g_sums[sb + 1], zv.y);
        atomicAdd(&g_sums[sb + 2], zv.z);
        atomicAdd(&g_sums[sb + 3], zv.w);
    }
    if (lane == 0 && idx_off >= 0) {
        int p = idx_off + row;
        if (p < out_size) out[p] = (float)id;
    }
    #pragma unroll
    for (int off = 16; off; off >>= 1)
        ls += __shfl_down_sync(0xffffffffu, ls, off);
    if (lane == 0) wsum[w] = ls;
    __syncthreads();
    if (tid == 0) {
        double t = 0.0;
        #pragma unroll
        for (int i = 0; i < 8; ++i) t += wsum[i];
        g_losspart[blockIdx.x] = t;
    }
}

// ---------------- kernel: m_t EMA update ---------------------------------------
__global__ void mt_kernel(const float* __restrict__ m_t, float* __restrict__ out,
                          int out_size, int mt_off) {
    int i = blockIdx.x * blockDim.x + threadIdx.x;
    if (i >= NE * EDIM || mt_off < 0) return;
    int j = i >> 8;
    float m = m_t[i];
    float val = (g_counts[j] > 0.0f) ? (m * 0.99f + g_sums[i] * 0.01f) : m;
    int p = mt_off + i;
    if (p < out_size) out[p] = val;
}

// ---------------- kernel: loss / perplexity / N_t -------------------------------
__global__ void finalize_kernel(const float* __restrict__ N_t, float* __restrict__ out,
                                int out_size, int loss_off, int perp_off, int nt_off) {
    __shared__ double red[1024];
    int tid = threadIdx.x;

    double s = 0.0;
    for (int i = tid; i < LOSSPARTS; i += 1024) s += g_losspart[i];
    red[tid] = s;
    __syncthreads();
    for (int st = 512; st > 0; st >>= 1) {
        if (tid < st) red[tid] += red[tid + st];
        __syncthreads();
    }
    double loss_sum = red[0];
    __syncthreads();

    float c = g_counts[tid];
    float em = c * (1.0f / 65536.0f);
    red[tid] = (double)(em * logf(em + 1e-10f));
    __syncthreads();
    for (int st = 512; st > 0; st >>= 1) {
        if (tid < st) red[tid] += red[tid + st];
        __syncthreads();
    }
    if (tid == 0) {
        if (loss_off >= 0 && loss_off < out_size)
            out[loss_off] = 0.25f * (float)(loss_sum / 16777216.0);
        if (perp_off >= 0 && perp_off < out_size)
            out[perp_off] = expf(-(float)red[0]);
    }
    if (nt_off >= 0) {
        float nt = N_t[tid];
        float val = (c > 0.0f) ? (nt * 0.99f + c * 0.01f) : nt;
        int p = nt_off + tid;
        if (p < out_size) out[p] = val;
    }
}

// ---------------- launcher -------------------------------------------------------
extern "C" void kernel_launch(void* const* d_in, const int* in_sizes, int n_in,
                              void* d_out, int out_size) {
    const float* z   = (const float*)d_in[0];   // [32,2048,256]
    const float* emb = (const float*)d_in[1];   // [1024,256]
    const float* N_t = (const float*)d_in[2];   // [1024]
    const float* m_t = (const float*)d_in[3];   // [1024,256]
    float* out = (float*)d_out;

    int loss_off, zq_off, idx_off, perp_off, nt_off, mt_off;
    if (out_size == NROWS * EDIM) {             // z_q_st only
        loss_off = -1; zq_off = 0; idx_off = -1; perp_off = -1; nt_off = -1; mt_off = -1;
    } else if (out_size == NROWS) {             // idx only
        loss_off = -1; zq_off = -1; idx_off = 0; perp_off = -1; nt_off = -1; mt_off = -1;
    } else {                                    // full tuple concat
        loss_off = OFF_LOSS; zq_off = OFF_ZQ; idx_off = OFF_IDX;
        perp_off = OFF_PERP; nt_off = OFF_NT; mt_off = OFF_MT;
    }

    zero_kernel<<<1024, 256>>>();
    enorm_kernel<<<4, 256>>>(emb);
    rownorm_kernel<<<NROWS / 8, 256>>>(z);
    argmin_kernel<<<NROWS / 64, 256>>>(z, emb);
    scatter_kernel<<<NROWS / 8, 256>>>(z, emb, out, out_size, zq_off, idx_off);
    mt_kernel<<<NE * EDIM / 256, 256>>>(m_t, out, out_size, mt_off);
    finalize_kernel<<<1, 1024>>>(N_t, out, out_size, loss_off, perp_off, nt_off);
}

// round 7
// speedup vs baseline: 1.3819x; 1.0392x over previous
#include <cuda_runtime.h>
#include <cuda_bf16.h>
#include <math.h>
#include <stdint.h>

typedef unsigned long long u64;

// Problem constants
#define NROWS   65536      // 32*2048 flattened z rows
#define EDIM    256
#define NE      1024
#define LOSSPARTS 8192
#define KT      8          // k-tile
#define ZPAD    66         // padded row-stride (u64) for zs to avoid STS conflicts

// Full-concat output layout (tuple order: loss, z_q_st, idx, perplexity, N_t, m_t)
#define OFF_LOSS 0
#define OFF_ZQ   1
#define OFF_IDX  16777217
#define OFF_PERP 16842753
#define OFF_NT   16842754
#define OFF_MT   16843778

// ---------------- scratch (__device__ globals: no allocations allowed) ----------
__device__ int    g_idx[NROWS];
__device__ float  g_rowa[NROWS];        // fl32(||z_row||^2)
__device__ float  g_enorm[NE];          // fl32(||e_j||^2)
__device__ float  g_counts[NE];
__device__ float  g_sums[NE * EDIM];
__device__ double g_losspart[LOSSPARTS];

// ---------------- packed fp32x2 helpers (Blackwell dual-FP32 pipe) --------------
__device__ __forceinline__ u64 ffma2(u64 a, u64 b, u64 c) {
    u64 d;
    asm("fma.rn.f32x2 %0, %1, %2, %3;" : "=l"(d) : "l"(a), "l"(b), "l"(c));
    return d;
}
__device__ __forceinline__ u64 dupf(float x) {
    unsigned xi = __float_as_uint(x);
    u64 d;
    asm("mov.b64 %0, {%1, %1};" : "=l"(d) : "r"(xi));
    return d;
}
__device__ __forceinline__ float2 unpack2(u64 v) {
    unsigned lo, hi;
    asm("mov.b64 {%0, %1}, %2;" : "=r"(lo), "=r"(hi) : "l"(v));
    float2 r; r.x = __uint_as_float(lo); r.y = __uint_as_float(hi);
    return r;
}

// ---------------- kernel: zero the accumulators --------------------------------
__global__ void zero_kernel() {
    int i = blockIdx.x * blockDim.x + threadIdx.x;     // grid covers 262144
    if (i < NE * EDIM) g_sums[i] = 0.0f;
    if (i < NE)        g_counts[i] = 0.0f;
    if (i < LOSSPARTS) g_losspart[i] = 0.0;
}

// ---------------- kernel: code norms ||e_j||^2 ----------------------------------
__global__ void enorm_kernel(const float* __restrict__ emb) {
    int i = blockIdx.x * blockDim.x + threadIdx.x;
    if (i >= NE) return;
    const float4* er = reinterpret_cast<const float4*>(emb + (size_t)i * EDIM);
    double s = 0.0;
    #pragma unroll 8
    for (int q = 0; q < EDIM / 4; ++q) {
        float4 v = er[q];
        s += (double)v.x * v.x; s += (double)v.y * v.y;
        s += (double)v.z * v.z; s += (double)v.w * v.w;
    }
    g_enorm[i] = (float)s;
}

// ---------------- kernel: row norms ||z_i||^2 (warp per row) --------------------
__global__ void rownorm_kernel(const float* __restrict__ z) {
    int tid  = threadIdx.x;
    int lane = tid & 31;
    int row  = blockIdx.x * 8 + (tid >> 5);
    if (row >= NROWS) return;
    const float4* zr = reinterpret_cast<const float4*>(z + (size_t)row * EDIM);
    double s = 0.0;
    #pragma unroll
    for (int j = 0; j < 2; ++j) {
        float4 v = zr[lane + 32 * j];
        s += (double)v.x * v.x; s += (double)v.y * v.y;
        s += (double)v.z * v.z; s += (double)v.w * v.w;
    }
    #pragma unroll
    for (int off = 16; off; off >>= 1)
        s += __shfl_down_sync(0xffffffffu, s, off);
    if (lane == 0) g_rowa[row] = (float)s;
}

// ---------------- kernel: fused distance GEMM + argmin (fp32x2, pipelined) ------
// Block: 256 threads (8 warps), 64 rows x 1024 codes (4 chunks of 256 codes).
// Warp w owns rows [8w, 8w+8); lane l owns codes {chunk*256 + 64j + 2l, +1 : j=0..3}.
// k-tile = 8, double-buffered smem, register prefetch of next tile's LDG.
// Running best per row is a packed u64 (float_bits(d)<<32 | code) kept in smem.
__global__ __launch_bounds__(256, 2)
void argmin_kernel(const float* __restrict__ z, const float* __restrict__ emb) {
    __shared__ u64   zs[2][KT * ZPAD];   // [buf][k][row] as (v,v) pairs (padded)
    __shared__ float es[2][KT * 256];    // [buf][k][code]
    __shared__ u64   sbest[64];          // packed best per row (8 warps x 8 rows)

    const int tid  = threadIdx.x;
    const int lane = tid & 31;
    const int warp = tid >> 5;                  // 0..7: row group
    const int rowbase = blockIdx.x * 64;
    const int myrow0  = rowbase + warp * 8;

    if (lane < 8) sbest[warp * 8 + lane] = ~0ull;

    // z tile loader (tid < 128): row = tid>>1 (0..63), k4 = (tid&1)*4
    const int zrow = tid >> 1;
    const int zk4  = (tid & 1) * 4;
    const float* zsrc = z + (size_t)(rowbase + zrow) * EDIM + zk4;
    const float* ebase = 0;  // set per chunk

    for (int cc = 0; cc < 4; ++cc) {
        u64 acc[8][4];
        #pragma unroll
        for (int r = 0; r < 8; ++r)
            #pragma unroll
            for (int j = 0; j < 4; ++j) acc[r][j] = 0ull;

        ebase = emb + (size_t)(cc * 256 + tid) * EDIM;

        // prefetch tile 0
        float4 pz, pe0, pe1;
        if (tid < 128) pz = *reinterpret_cast<const float4*>(zsrc);
        pe0 = *reinterpret_cast<const float4*>(ebase);
        pe1 = *reinterpret_cast<const float4*>(ebase + 4);

        __syncthreads();   // previous chunk's readers of buf0 are done
        // STS tile 0 -> buf 0
        if (tid < 128) {
            u64* zd = zs[0];
            zd[(zk4 + 0) * ZPAD + zrow] = dupf(pz.x);
            zd[(zk4 + 1) * ZPAD + zrow] = dupf(pz.y);
            zd[(zk4 + 2) * ZPAD + zrow] = dupf(pz.z);
            zd[(zk4 + 3) * ZPAD + zrow] = dupf(pz.w);
        }
        {
            float* ed = es[0];
            ed[0 * 256 + tid] = pe0.x;
            ed[1 * 256 + tid] = pe0.y;
            ed[2 * 256 + tid] = pe0.z;
            ed[3 * 256 + tid] = pe0.w;
            ed[4 * 256 + tid] = pe1.x;
            ed[5 * 256 + tid] = pe1.y;
            ed[6 * 256 + tid] = pe1.z;
            ed[7 * 256 + tid] = pe1.w;
        }

        for (int t = 0; t < 32; ++t) {
            // prefetch tile t+1 (LDG hidden under this tile's compute)
            if (t < 31) {
                int kb = (t + 1) * KT;
                if (tid < 128) pz = *reinterpret_cast<const float4*>(zsrc + kb);
                pe0 = *reinterpret_cast<const float4*>(ebase + kb);
                pe1 = *reinterpret_cast<const float4*>(ebase + kb + 4);
            }

            __syncthreads();   // tile t's STS visible; buf[(t+1)&1] readers done

            // compute tile t from buf[t&1]
            {
                const u64* zb = zs[t & 1];
                const u64* eb = reinterpret_cast<const u64*>(es[t & 1]);
                #pragma unroll
                for (int k = 0; k < KT; ++k) {
                    const ulonglong2* zp = reinterpret_cast<const ulonglong2*>(
                        zb + k * ZPAD + warp * 8);
                    ulonglong2 z01 = zp[0], z23 = zp[1], z45 = zp[2], z67 = zp[3];
                    u64 e0 = eb[k * 128 + lane];
                    u64 e1 = eb[k * 128 + lane + 32];
                    u64 e2 = eb[k * 128 + lane + 64];
                    u64 e3 = eb[k * 128 + lane + 96];
                    acc[0][0] = ffma2(z01.x, e0, acc[0][0]);
                    acc[0][1] = ffma2(z01.x, e1, acc[0][1]);
                    acc[0][2] = ffma2(z01.x, e2, acc[0][2]);
                    acc[0][3] = ffma2(z01.x, e3, acc[0][3]);
                    acc[1][0] = ffma2(z01.y, e0, acc[1][0]);
                    acc[1][1] = ffma2(z01.y, e1, acc[1][1]);
                    acc[1][2] = ffma2(z01.y, e2, acc[1][2]);
                    acc[1][3] = ffma2(z01.y, e3, acc[1][3]);
                    acc[2][0] = ffma2(z23.x, e0, acc[2][0]);
                    acc[2][1] = ffma2(z23.x, e1, acc[2][1]);
                    acc[2][2] = ffma2(z23.x, e2, acc[2][2]);
                    acc[2][3] = ffma2(z23.x, e3, acc[2][3]);
                    acc[3][0] = ffma2(z23.y, e0, acc[3][0]);
                    acc[3][1] = ffma2(z23.y, e1, acc[3][1]);
                    acc[3][2] = ffma2(z23.y, e2, acc[3][2]);
                    acc[3][3] = ffma2(z23.y, e3, acc[3][3]);
                    acc[4][0] = ffma2(z45.x, e0, acc[4][0]);
                    acc[4][1] = ffma2(z45.x, e1, acc[4][1]);
                    acc[4][2] = ffma2(z45.x, e2, acc[4][2]);
                    acc[4][3] = ffma2(z45.x, e3, acc[4][3]);
                    acc[5][0] = ffma2(z45.y, e0, acc[5][0]);
                    acc[5][1] = ffma2(z45.y, e1, acc[5][1]);
                    acc[5][2] = ffma2(z45.y, e2, acc[5][2]);
                    acc[5][3] = ffma2(z45.y, e3, acc[5][3]);
                    acc[6][0] = ffma2(z67.x, e0, acc[6][0]);
                    acc[6][1] = ffma2(z67.x, e1, acc[6][1]);
                    acc[6][2] = ffma2(z67.x, e2, acc[6][2]);
                    acc[6][3] = ffma2(z67.x, e3, acc[6][3]);
                    acc[7][0] = ffma2(z67.y, e0, acc[7][0]);
                    acc[7][1] = ffma2(z67.y, e1, acc[7][1]);
                    acc[7][2] = ffma2(z67.y, e2, acc[7][2]);
                    acc[7][3] = ffma2(z67.y, e3, acc[7][3]);
                }
            }

            // STS tile t+1 -> buf[(t+1)&1] (readers of that buf finished at t-1)
            if (t < 31) {
                if (tid < 128) {
                    u64* zd = zs[(t + 1) & 1];
                    zd[(zk4 + 0) * ZPAD + zrow] = dupf(pz.x);
                    zd[(zk4 + 1) * ZPAD + zrow] = dupf(pz.y);
                    zd[(zk4 + 2) * ZPAD + zrow] = dupf(pz.z);
                    zd[(zk4 + 3) * ZPAD + zrow] = dupf(pz.w);
                }
                float* ed = es[(t + 1) & 1];
                ed[0 * 256 + tid] = pe0.x;
                ed[1 * 256 + tid] = pe0.y;
                ed[2 * 256 + tid] = pe0.z;
                ed[3 * 256 + tid] = pe0.w;
                ed[4 * 256 + tid] = pe1.x;
                ed[5 * 256 + tid] = pe1.y;
                ed[6 * 256 + tid] = pe1.z;
                ed[7 * 256 + tid] = pe1.w;
            }
        }

        // epilogue: same fp expression as before -> bit-identical distances
        {
            float a[8];
            #pragma unroll
            for (int r = 0; r < 8; ++r) a[r] = g_rowa[myrow0 + r];
            u64 b[8];
            #pragma unroll
            for (int r = 0; r < 8; ++r) b[r] = ~0ull;

            #pragma unroll
            for (int j = 0; j < 4; ++j) {
                int c0 = cc * 256 + j * 64 + lane * 2;
                float2 bb = *reinterpret_cast<const float2*>(&g_enorm[c0]);
                #pragma unroll
                for (int r = 0; r < 8; ++r) {
                    float2 m = unpack2(acc[r][j]);
                    float d0 = (a[r] + bb.x) - 2.0f * m.x;
                    float d1 = (a[r] + bb.y) - 2.0f * m.y;
                    u64 p0 = ((u64)__float_as_uint(d0) << 32) | (unsigned)c0;
                    u64 p1 = ((u64)__float_as_uint(d1) << 32) | (unsigned)(c0 + 1);
                    if (p0 < b[r]) b[r] = p0;
                    if (p1 < b[r]) b[r] = p1;
                }
            }
            #pragma unroll
            for (int r = 0; r < 8; ++r) {
                u64 v = b[r];
                #pragma unroll
                for (int off = 16; off; off >>= 1) {
                    u64 o = __shfl_down_sync(0xffffffffu, v, off);
                    if (o < v) v = o;
                }
                if (lane == 0) {
                    if (v < sbest[warp * 8 + r]) sbest[warp * 8 + r] = v;
                }
            }
        }
    }

    __syncwarp();
    if (lane < 8) {
        u64 p = sbest[warp * 8 + lane];
        int id = (int)(unsigned)(p & 0xffffffffull);
        g_idx[myrow0 + lane] = id;
        atomicAdd(&g_counts[id], 1.0f);
    }
}

// ---------------- kernel: gather z_q, straight-through, loss, segment sums ------
__global__ void scatter_kernel(const float* __restrict__ z, const float* __restrict__ emb,
                               float* __restrict__ out, int out_size,
                               int zq_off, int idx_off) {
    __shared__ double wsum[8];
    int tid  = threadIdx.x;
    int lane = tid & 31;
    int w    = tid >> 5;
    int row  = blockIdx.x * 8 + w;

    int id = g_idx[row];
    const float4* zr = reinterpret_cast<const float4*>(z + (size_t)row * EDIM);
    const float4* er = reinterpret_cast<const float4*>(emb + (size_t)id * EDIM);

    double ls = 0.0;
    #pragma unroll
    for (int j = 0; j < 2; ++j) {
        int c4 = lane + 32 * j;
        float4 zv = zr[c4];
        float4 ev = er[c4];
        float dx = ev.x - zv.x, dy = ev.y - zv.y, dz = ev.z - zv.z, dw = ev.w - zv.w;
        if (zq_off >= 0) {
            int base = zq_off + row * EDIM + c4 * 4;
            if (base + 3 < out_size) {
                out[base + 0] = zv.x + dx;
                out[base + 1] = zv.y + dy;
                out[base + 2] = zv.z + dz;
                out[base + 3] = zv.w + dw;
            }
        }
        ls += (double)dx * dx + (double)dy * dy + (double)dz * dz + (double)dw * dw;
        int sb = id * EDIM + c4 * 4;
        atomicAdd(&g_sums[sb + 0], zv.x);
        atomicAdd(&g_sums[sb + 1], zv.y);
        atomicAdd(&g_sums[sb + 2], zv.z);
        atomicAdd(&g_sums[sb + 3], zv.w);
    }
    if (lane == 0 && idx_off >= 0) {
        int p = idx_off + row;
        if (p < out_size) out[p] = (float)id;
    }
    #pragma unroll
    for (int off = 16; off; off >>= 1)
        ls += __shfl_down_sync(0xffffffffu, ls, off);
    if (lane == 0) wsum[w] = ls;
    __syncthreads();
    if (tid == 0) {
        double t = 0.0;
        #pragma unroll
        for (int i = 0; i < 8; ++i) t += wsum[i];
        g_losspart[blockIdx.x] = t;
    }
}

// ---------------- kernel: m_t EMA update ---------------------------------------
__global__ void mt_kernel(const float* __restrict__ m_t, float* __restrict__ out,
                          int out_size, int mt_off) {
    int i = blockIdx.x * blockDim.x + threadIdx.x;
    if (i >= NE * EDIM || mt_off < 0) return;
    int j = i >> 8;
    float m = m_t[i];
    float val = (g_counts[j] > 0.0f) ? (m * 0.99f + g_sums[i] * 0.01f) : m;
    int p = mt_off + i;
    if (p < out_size) out[p] = val;
}

// ---------------- kernel: loss / perplexity / N_t -------------------------------
__global__ void finalize_kernel(const float* __restrict__ N_t, float* __restrict__ out,
                                int out_size, int loss_off, int perp_off, int nt_off) {
    __shared__ double red[1024];
    int tid = threadIdx.x;

    double s = 0.0;
    for (int i = tid; i < LOSSPARTS; i += 1024) s += g_losspart[i];
    red[tid] = s;
    __syncthreads();
    for (int st = 512; st > 0; st >>= 1) {
        if (tid < st) red[tid] += red[tid + st];
        __syncthreads();
    }
    double loss_sum = red[0];
    __syncthreads();

    float c = g_counts[tid];
    float em = c * (1.0f / 65536.0f);
    red[tid] = (double)(em * logf(em + 1e-10f));
    __syncthreads();
    for (int st = 512; st > 0; st >>= 1) {
        if (tid < st) red[tid] += red[tid + st];
        __syncthreads();
    }
    if (tid == 0) {
        if (loss_off >= 0 && loss_off < out_size)
            out[loss_off] = 0.25f * (float)(loss_sum / 16777216.0);
        if (perp_off >= 0 && perp_off < out_size)
            out[perp_off] = expf(-(float)red[0]);
    }
    if (nt_off >= 0) {
        float nt = N_t[tid];
        float val = (c > 0.0f) ? (nt * 0.99f + c * 0.01f) : nt;
        int p = nt_off + tid;
        if (p < out_size) out[p] = val;
    }
}

// ---------------- launcher -------------------------------------------------------
extern "C" void kernel_launch(void* const* d_in, const int* in_sizes, int n_in,
                              void* d_out, int out_size) {
    const float* z   = (const float*)d_in[0];   // [32,2048,256]
    const float* emb = (const float*)d_in[1];   // [1024,256]
    const float* N_t = (const float*)d_in[2];   // [1024]
    const float* m_t = (const float*)d_in[3];   // [1024,256]
    float* out = (float*)d_out;

    int loss_off, zq_off, idx_off, perp_off, nt_off, mt_off;
    if (out_size == NROWS * EDIM) {             // z_q_st only
        loss_off = -1; zq_off = 0; idx_off = -1; perp_off = -1; nt_off = -1; mt_off = -1;
    } else if (out_size == NROWS) {             // idx only
        loss_off = -1; zq_off = -1; idx_off = 0; perp_off = -1; nt_off = -1; mt_off = -1;
    } else {                                    // full tuple concat
        loss_off = OFF_LOSS; zq_off = OFF_ZQ; idx_off = OFF_IDX;
        perp_off = OFF_PERP; nt_off = OFF_NT; mt_off = OFF_MT;
    }

    zero_kernel<<<1024, 256>>>();
    enorm_kernel<<<4, 256>>>(emb);
    rownorm_kernel<<<NROWS / 8, 256>>>(z);
    argmin_kernel<<<NROWS / 64, 256>>>(z, emb);
    scatter_kernel<<<NROWS / 8, 256>>>(z, emb, out, out_size, zq_off, idx_off);
    mt_kernel<<<NE * EDIM / 256, 256>>>(m_t, out, out_size, mt_off);
    finalize_kernel<<<1, 1024>>>(N_t, out, out_size, loss_off, perp_off, nt_off);
}

// round 11
// speedup vs baseline: 2.4591x; 1.7795x over previous
#include <cuda_runtime.h>
#include <cuda_bf16.h>
#include <math.h>
#include <stdint.h>

typedef unsigned long long u64;
typedef unsigned int u32;

// Problem constants
#define NROWS   65536      // 32*2048 flattened z rows
#define EDIM    256
#define NE      1024
#define LOSSPARTS 8192
#define MARGIN  4e-3f      // rescore margin (worst-case approx error ~1.3e-3)

// Full-concat output layout (tuple order: loss, z_q_st, idx, perplexity, N_t, m_t)
#define OFF_LOSS 0
#define OFF_ZQ   1
#define OFF_IDX  16777217
#define OFF_PERP 16842753
#define OFF_NT   16842754
#define OFF_MT   16843778

// ---------------- scratch (__device__ globals: no allocations allowed) ----------
__device__ int    g_idx[NROWS];
__device__ float  g_rowa[NROWS];        // fl32(||z_row||^2)
__device__ float  g_enorm[NE];          // fl32(||e_j||^2)
__device__ float  g_counts[NE];
__device__ float  g_sums[NE * EDIM];
__device__ double g_losspart[LOSSPARTS];
__device__ u64    g_best[NROWS];        // approx packed (dist_bits<<32 | code)
__device__ u64    g_bestx[NROWS];       // exact packed best
__device__ float  g_dist[(size_t)NROWS * NE];   // approx distance matrix (256MB)
// bf16 hi parts
__device__ __nv_bfloat16 g_zh[NROWS * EDIM];
__device__ __nv_bfloat16 g_eh[NE * EDIM];

// ---------------- PTX helpers ----------------------------------------------------
__device__ __forceinline__ u32 smem_u32(const void* p) {
    u32 a;
    asm("{ .reg .u64 t; cvta.to.shared.u64 t, %1; cvt.u32.u64 %0, t; }" : "=r"(a) : "l"(p));
    return a;
}
__device__ __forceinline__ void ldmx4(u32* r, u32 addr) {
    asm volatile("ldmatrix.sync.aligned.m8n8.x4.shared.b16 {%0,%1,%2,%3}, [%4];"
                 : "=r"(r[0]), "=r"(r[1]), "=r"(r[2]), "=r"(r[3]) : "r"(addr));
}
__device__ __forceinline__ void mma_bf16(float* c, const u32* a, const u32* b) {
    asm volatile(
        "mma.sync.aligned.m16n8k16.row.col.f32.bf16.bf16.f32 "
        "{%0,%1,%2,%3}, {%4,%5,%6,%7}, {%8,%9}, {%0,%1,%2,%3};"
        : "+f"(c[0]), "+f"(c[1]), "+f"(c[2]), "+f"(c[3])
        : "r"(a[0]), "r"(a[1]), "r"(a[2]), "r"(a[3]), "r"(b[0]), "r"(b[1]));
}
__device__ __forceinline__ u64 pack_bf4(const float* f) {
    unsigned short h0 = __bfloat16_as_ushort(__float2bfloat16(f[0]));
    unsigned short h1 = __bfloat16_as_ushort(__float2bfloat16(f[1]));
    unsigned short h2 = __bfloat16_as_ushort(__float2bfloat16(f[2]));
    unsigned short h3 = __bfloat16_as_ushort(__float2bfloat16(f[3]));
    return (u64)h0 | ((u64)h1 << 16) | ((u64)h2 << 32) | ((u64)h3 << 48);
}

// ---------------- kernel: zero / init --------------------------------------------
__global__ void zero_kernel() {
    int i = blockIdx.x * blockDim.x + threadIdx.x;     // grid covers 262144
    if (i < NE * EDIM) g_sums[i] = 0.0f;
    if (i < NE)        g_counts[i] = 0.0f;
    if (i < LOSSPARTS) g_losspart[i] = 0.0;
    if (i < NROWS)   { g_best[i] = ~0ull; g_bestx[i] = ~0ull; }
}

// ---------------- kernel: z prep — row norms + bf16 split (warp per row) --------
__global__ void prep_z_kernel(const float* __restrict__ z) {
    int tid  = threadIdx.x;
    int lane = tid & 31;
    int row  = blockIdx.x * 8 + (tid >> 5);
    const float4* zr = reinterpret_cast<const float4*>(z + (size_t)row * EDIM);
    double s = 0.0;
    #pragma unroll
    for (int j = 0; j < 2; ++j) {
        int c4 = lane + 32 * j;
        float4 v = zr[c4];
        float f[4] = { v.x, v.y, v.z, v.w };
        s += (double)v.x * v.x; s += (double)v.y * v.y;
        s += (double)v.z * v.z; s += (double)v.w * v.w;
        *reinterpret_cast<u64*>(g_zh + (size_t)row * EDIM + c4 * 4) = pack_bf4(f);
    }
    #pragma unroll
    for (int off = 16; off; off >>= 1)
        s += __shfl_down_sync(0xffffffffu, s, off);
    if (lane == 0) g_rowa[row] = (float)s;
}

// ---------------- kernel: e prep — code norms + bf16 split (warp per row) -------
__global__ void prep_e_kernel(const float* __restrict__ emb) {
    int tid  = threadIdx.x;
    int lane = tid & 31;
    int row  = blockIdx.x * 8 + (tid >> 5);
    if (row >= NE) return;
    const float4* er = reinterpret_cast<const float4*>(emb + (size_t)row * EDIM);
    double s = 0.0;
    #pragma unroll
    for (int j = 0; j < 2; ++j) {
        int c4 = lane + 32 * j;
        float4 v = er[c4];
        float f[4] = { v.x, v.y, v.z, v.w };
        s += (double)v.x * v.x; s += (double)v.y * v.y;
        s += (double)v.z * v.z; s += (double)v.w * v.w;
        *reinterpret_cast<u64*>(g_eh + (size_t)row * EDIM + c4 * 4) = pack_bf4(f);
    }
    #pragma unroll
    for (int off = 16; off; off >>= 1)
        s += __shfl_down_sync(0xffffffffu, s, off);
    if (lane == 0) g_enorm[row] = (float)s;
}

// ---------------- kernel: approx bf16 MMA distance GEMM -------------------------
// Grid (16, 512): blockIdx.x = 64-code tile, blockIdx.y = 128-row tile.
// 256 threads = 8 warps as 4(m) x 2(n); warp tile 32 rows x 32 codes.
// Single-term zh*eh, fp32 accumulate. Writes full approx distance matrix +
// per-row packed approx min (atomicMin).
__global__ __launch_bounds__(256, 2)
void argmin_mma_kernel() {
    __shared__ __align__(16) unsigned short sAh[128 * 40];
    __shared__ __align__(16) unsigned short sBh[64 * 40];

    const int tid  = threadIdx.x;
    const int lane = tid & 31;
    const int warp = tid >> 5;
    const int wm = warp >> 1;            // 0..3
    const int wn = warp & 1;             // 0..1
    const int R = blockIdx.y * 128;
    const int C = blockIdx.x * 64;

    float acc[2][4][4];
    #pragma unroll
    for (int mt = 0; mt < 2; ++mt)
        #pragma unroll
        for (int nt = 0; nt < 4; ++nt)
            #pragma unroll
            for (int j = 0; j < 4; ++j) acc[mt][nt][j] = 0.0f;

    const int a_m = ((lane >> 3) & 1) * 8 + (lane & 7);
    const int a_k = (lane >> 4) * 8;
    const int b_n = (lane >> 4) * 8 + (lane & 7);
    const int b_k = ((lane >> 3) & 1) * 8;

    const u32 sAh_b = smem_u32(sAh);
    const u32 sBh_b = smem_u32(sBh);

    const int a_row = tid >> 2, a_q = tid & 3;
    for (int kt = 0; kt < 8; ++kt) {
        __syncthreads();
        #pragma unroll
        for (int i = 0; i < 2; ++i) {
            int row = a_row + i * 64;
            const float4* ph = reinterpret_cast<const float4*>(
                g_zh + (size_t)(R + row) * EDIM + kt * 32) + a_q;
            *reinterpret_cast<float4*>(sAh + row * 40 + a_q * 8) = *ph;
        }
        {
            int row = tid >> 2, q = tid & 3;
            const float4* ph = reinterpret_cast<const float4*>(
                g_eh + (size_t)(C + row) * EDIM + kt * 32) + q;
            *reinterpret_cast<float4*>(sBh + row * 40 + q * 8) = *ph;
        }
        __syncthreads();

        #pragma unroll
        for (int k16 = 0; k16 < 2; ++k16) {
            const int kb = k16 * 16;
            u32 ah[2][4], bh[2][4];
            #pragma unroll
            for (int mt = 0; mt < 2; ++mt) {
                u32 off = (u32)(((wm * 32 + mt * 16 + a_m) * 40 + kb + a_k) * 2);
                ldmx4(ah[mt], sAh_b + off);
            }
            #pragma unroll
            for (int h = 0; h < 2; ++h) {
                u32 off = (u32)(((wn * 32 + h * 16 + b_n) * 40 + kb + b_k) * 2);
                ldmx4(bh[h], sBh_b + off);
            }
            #pragma unroll
            for (int mt = 0; mt < 2; ++mt)
                #pragma unroll
                for (int nt = 0; nt < 4; ++nt)
                    mma_bf16(acc[mt][nt], ah[mt], &bh[nt >> 1][(nt & 1) * 2]);
        }
    }

    // ---------------- epilogue: d = (a+b) - 2m; store + packed argmin ------------
    const int tq = lane >> 2, tr = lane & 3;
    float bb[4][2];
    #pragma unroll
    for (int nt = 0; nt < 4; ++nt) {
        int c0 = C + wn * 32 + nt * 8 + tr * 2;
        bb[nt][0] = g_enorm[c0];
        bb[nt][1] = g_enorm[c0 + 1];
    }
    #pragma unroll
    for (int mt = 0; mt < 2; ++mt) {
        int row0 = R + wm * 32 + mt * 16 + tq;
        float a0 = g_rowa[row0];
        float a1 = g_rowa[row0 + 8];
        u64 p0 = ~0ull, p1 = ~0ull;
        #pragma unroll
        for (int nt = 0; nt < 4; ++nt) {
            int c0 = C + wn * 32 + nt * 8 + tr * 2;
            float d00 = (a0 + bb[nt][0]) - 2.0f * acc[mt][nt][0];
            float d01 = (a0 + bb[nt][1]) - 2.0f * acc[mt][nt][1];
            float d10 = (a1 + bb[nt][0]) - 2.0f * acc[mt][nt][2];
            float d11 = (a1 + bb[nt][1]) - 2.0f * acc[mt][nt][3];
            *reinterpret_cast<float2*>(&g_dist[(size_t)row0 * NE + c0]) =
                make_float2(d00, d01);
            *reinterpret_cast<float2*>(&g_dist[(size_t)(row0 + 8) * NE + c0]) =
                make_float2(d10, d11);
            u64 pk;
            pk = ((u64)__float_as_uint(d00) << 32) | (u32)c0;       if (pk < p0) p0 = pk;
            pk = ((u64)__float_as_uint(d01) << 32) | (u32)(c0 + 1); if (pk < p0) p0 = pk;
            pk = ((u64)__float_as_uint(d10) << 32) | (u32)c0;       if (pk < p1) p1 = pk;
            pk = ((u64)__float_as_uint(d11) << 32) | (u32)(c0 + 1); if (pk < p1) p1 = pk;
        }
        #pragma unroll
        for (int off = 1; off < 4; off <<= 1) {
            u64 o0 = __shfl_xor_sync(0xffffffffu, p0, off);
            u64 o1 = __shfl_xor_sync(0xffffffffu, p1, off);
            if (o0 < p0) p0 = o0;
            if (o1 < p1) p1 = o1;
        }
        if (tr == 0) {
            atomicMin(&g_best[row0], p0);
            atomicMin(&g_best[row0 + 8], p1);
        }
    }
}

// ---------------- kernel: exact rescore of near-min candidates ------------------
// Warp per row: scan 1024 approx distances, rescore codes within MARGIN of the
// approx min with an exact sequential-k fp32 FMA dot (same arithmetic order and
// epilogue expression as the known-exact R5 kernel).
__global__ __launch_bounds__(256, 4)
void rescore_kernel(const float* __restrict__ z, const float* __restrict__ emb) {
    __shared__ u32 list[8][128];
    __shared__ int cnt[8];
    const int tid  = threadIdx.x;
    const int lane = tid & 31;
    const int w    = tid >> 5;
    const int row  = blockIdx.x * 8 + w;

    if (lane == 0) cnt[w] = 0;
    __syncwarp();

    const float dmin = __uint_as_float((u32)(g_best[row] >> 32));
    const float thr = dmin + MARGIN;
    const float4* dr = reinterpret_cast<const float4*>(g_dist + (size_t)row * NE);
    #pragma unroll
    for (int q = 0; q < 8; ++q) {
        float4 dv = dr[q * 32 + lane];
        int cbase = (q * 32 + lane) * 4;
        if (dv.x <= thr) { int p = atomicAdd(&cnt[w], 1); if (p < 128) list[w][p] = cbase; }
        if (dv.y <= thr) { int p = atomicAdd(&cnt[w], 1); if (p < 128) list[w][p] = cbase + 1; }
        if (dv.z <= thr) { int p = atomicAdd(&cnt[w], 1); if (p < 128) list[w][p] = cbase + 2; }
        if (dv.w <= thr) { int p = atomicAdd(&cnt[w], 1); if (p < 128) list[w][p] = cbase + 3; }
    }
    __syncwarp();

    int n = cnt[w]; if (n > 128) n = 128;
    const float a = g_rowa[row];
    const float* zr = z + (size_t)row * EDIM;
    u64 best = ~0ull;
    for (int c = lane; c < n; c += 32) {
        int code = list[w][c];
        const float* er = emb + (size_t)code * EDIM;
        float m = 0.0f;
        #pragma unroll 8
        for (int k = 0; k < EDIM; ++k) m = fmaf(zr[k], er[k], m);
        float d = (a + g_enorm[code]) - 2.0f * m;
        u64 p = ((u64)__float_as_uint(d) << 32) | (u32)code;
        if (p < best) best = p;
    }
    #pragma unroll
    for (int off = 16; off; off >>= 1) {
        u64 o = __shfl_down_sync(0xffffffffu, best, off);
        if (o < best) best = o;
    }
    if (lane == 0) g_bestx[row] = best;
}

// ---------------- kernel: unpack best -> idx + counts ---------------------------
__global__ void idx_kernel() {
    int row = blockIdx.x * blockDim.x + threadIdx.x;
    if (row >= NROWS) return;
    int id = (int)(u32)(g_bestx[row] & 0xffffffffull);
    g_idx[row] = id;
    atomicAdd(&g_counts[id], 1.0f);
}

// ---------------- kernel: gather z_q, straight-through, loss, segment sums ------
__global__ void scatter_kernel(const float* __restrict__ z, const float* __restrict__ emb,
                               float* __restrict__ out, int out_size,
                               int zq_off, int idx_off) {
    __shared__ double wsum[8];
    int tid  = threadIdx.x;
    int lane = tid & 31;
    int w    = tid >> 5;
    int row  = blockIdx.x * 8 + w;

    int id = g_idx[row];
    const float4* zr = reinterpret_cast<const float4*>(z + (size_t)row * EDIM);
    const float4* er = reinterpret_cast<const float4*>(emb + (size_t)id * EDIM);

    double ls = 0.0;
    #pragma unroll
    for (int j = 0; j < 2; ++j) {
        int c4 = lane + 32 * j;
        float4 zv = zr[c4];
        float4 ev = er[c4];
        float dx = ev.x - zv.x, dy = ev.y - zv.y, dz = ev.z - zv.z, dw = ev.w - zv.w;
        if (zq_off >= 0) {
            int base = zq_off + row * EDIM + c4 * 4;
            if (base + 3 < out_size) {
                out[base + 0] = zv.x + dx;
                out[base + 1] = zv.y + dy;
                out[base + 2] = zv.z + dz;
                out[base + 3] = zv.w + dw;
            }
        }
        ls += (double)dx * dx + (double)dy * dy + (double)dz * dz + (double)dw * dw;
        int sb = id * EDIM + c4 * 4;
        atomicAdd(&g_sums[sb + 0], zv.x);
        atomicAdd(&g_sums[sb + 1], zv.y);
        atomicAdd(&g_sums[sb + 2], zv.z);
        atomicAdd(&g_sums[sb + 3], zv.w);
    }
    if (lane == 0 && idx_off >= 0) {
        int p = idx_off + row;
        if (p < out_size) out[p] = (float)id;
    }
    #pragma unroll
    for (int off = 16; off; off >>= 1)
        ls += __shfl_down_sync(0xffffffffu, ls, off);
    if (lane == 0) wsum[w] = ls;
    __syncthreads();
    if (tid == 0) {
        double t = 0.0;
        #pragma unroll
        for (int i = 0; i < 8; ++i) t += wsum[i];
        g_losspart[blockIdx.x] = t;
    }
}

// ---------------- kernel: m_t EMA update ---------------------------------------
__global__ void mt_kernel(const float* __restrict__ m_t, float* __restrict__ out,
                          int out_size, int mt_off) {
    int i = blockIdx.x * blockDim.x + threadIdx.x;
    if (i >= NE * EDIM || mt_off < 0) return;
    int j = i >> 8;
    float m = m_t[i];
    float val = (g_counts[j] > 0.0f) ? (m * 0.99f + g_sums[i] * 0.01f) : m;
    int p = mt_off + i;
    if (p < out_size) out[p] = val;
}

// ---------------- kernel: loss / perplexity / N_t -------------------------------
__global__ void finalize_kernel(const float* __restrict__ N_t, float* __restrict__ out,
                                int out_size, int loss_off, int perp_off, int nt_off) {
    __shared__ double red[1024];
    int tid = threadIdx.x;

    double s = 0.0;
    for (int i = tid; i < LOSSPARTS; i += 1024) s += g_losspart[i];
    red[tid] = s;
    __syncthreads();
    for (int st = 512; st > 0; st >>= 1) {
        if (tid < st) red[tid] += red[tid + st];
        __syncthreads();
    }
    double loss_sum = red[0];
    __syncthreads();

    float c = g_counts[tid];
    float em = c * (1.0f / 65536.0f);
    red[tid] = (double)(em * logf(em + 1e-10f));
    __syncthreads();
    for (int st = 512; st > 0; st >>= 1) {
        if (tid < st) red[tid] += red[tid + st];
        __syncthreads();
    }
    if (tid == 0) {
        if (loss_off >= 0 && loss_off < out_size)
            out[loss_off] = 0.25f * (float)(loss_sum / 16777216.0);
        if (perp_off >= 0 && perp_off < out_size)
            out[perp_off] = expf(-(float)red[0]);
    }
    if (nt_off >= 0) {
        float nt = N_t[tid];
        float val = (c > 0.0f) ? (nt * 0.99f + c * 0.01f) : nt;
        int p = nt_off + tid;
        if (p < out_size) out[p] = val;
    }
}

// ---------------- launcher -------------------------------------------------------
extern "C" void kernel_launch(void* const* d_in, const int* in_sizes, int n_in,
                              void* d_out, int out_size) {
    const float* z   = (const float*)d_in[0];   // [32,2048,256]
    const float* emb = (const float*)d_in[1];   // [1024,256]
    const float* N_t = (const float*)d_in[2];   // [1024]
    const float* m_t = (const float*)d_in[3];   // [1024,256]
    float* out = (float*)d_out;

    int loss_off, zq_off, idx_off, perp_off, nt_off, mt_off;
    if (out_size == NROWS * EDIM) {             // z_q_st only
        loss_off = -1; zq_off = 0; idx_off = -1; perp_off = -1; nt_off = -1; mt_off = -1;
    } else if (out_size == NROWS) {             // idx only
        loss_off = -1; zq_off = -1; idx_off = 0; perp_off = -1; nt_off = -1; mt_off = -1;
    } else {                                    // full tuple concat
        loss_off = OFF_LOSS; zq_off = OFF_ZQ; idx_off = OFF_IDX;
        perp_off = OFF_PERP; nt_off = OFF_NT; mt_off = OFF_MT;
    }

    zero_kernel<<<1024, 256>>>();
    prep_e_kernel<<<NE / 8, 256>>>(emb);
    prep_z_kernel<<<NROWS / 8, 256>>>(z);
    {
        dim3 grid(16, 512);
        argmin_mma_kernel<<<grid, 256>>>();
    }
    rescore_kernel<<<NROWS / 8, 256>>>(z, emb);
    idx_kernel<<<NROWS / 256, 256>>>();
    scatter_kernel<<<NROWS / 8, 256>>>(z, emb, out, out_size, zq_off, idx_off);
    mt_kernel<<<NE * EDIM / 256, 256>>>(m_t, out, out_size, mt_off);
    finalize_kernel<<<1, 1024>>>(N_t, out, out_size, loss_off, perp_off, nt_off);
}